// round 6
// baseline (speedup 1.0000x reference)
#include <cuda_runtime.h>
#include <cuda_bf16.h>
#include <cuda_fp16.h>
#include <stdint.h>
#include <math.h>

#define BATCH 2
#define D 256
#define NH 8
#define DH 32
#define NL 4
#define NP 4
#define NLAYERS 6
#define DFF 1024
#define S_TOTAL 21760
#define M_ROWS (BATCH * S_TOTAL)   // 43520

__device__ __constant__ int c_lvl_h[NL]     = {128, 64, 32, 16};
__device__ __constant__ int c_lvl_w[NL]     = {128, 64, 32, 16};
__device__ __constant__ int c_lvl_start[NL] = {0, 16384, 20480, 21504};

// ---------------------------------------------------------------------------
// Scratch
// ---------------------------------------------------------------------------
__device__ __align__(128) float g_pos    [(size_t)M_ROWS * D];
__device__ __align__(128) float g_out    [(size_t)M_ROWS * D];
__device__ __align__(128) __half g_value [(size_t)M_ROWS * D];
__device__ __align__(128) float g_offattn[(size_t)M_ROWS * 384];
__device__ __align__(128) float g_proj   [(size_t)M_ROWS * D];
__device__ __align__(128) float g_ffn2   [(size_t)M_ROWS * D];

__device__ __align__(128) __nv_bfloat16 g_out_hi [(size_t)M_ROWS * D];
__device__ __align__(128) __nv_bfloat16 g_out_lo [(size_t)M_ROWS * D];
__device__ __align__(128) __nv_bfloat16 g_q_hi   [(size_t)M_ROWS * D];
__device__ __align__(128) __nv_bfloat16 g_q_lo   [(size_t)M_ROWS * D];
__device__ __align__(128) __nv_bfloat16 g_ln1_hi [(size_t)M_ROWS * D];
__device__ __align__(128) __nv_bfloat16 g_ln1_lo [(size_t)M_ROWS * D];
__device__ __align__(128) __nv_bfloat16 g_attn_hi[(size_t)M_ROWS * D];
__device__ __align__(128) __nv_bfloat16 g_attn_lo[(size_t)M_ROWS * D];
__device__ __align__(128) __nv_bfloat16 g_f1_hi  [(size_t)M_ROWS * DFF];
__device__ __align__(128) __nv_bfloat16 g_f1_lo  [(size_t)M_ROWS * DFF];

__device__ __align__(128) __nv_bfloat16 g_WvalT_hi [NLAYERS * 256 * 256];
__device__ __align__(128) __nv_bfloat16 g_WvalT_lo [NLAYERS * 256 * 256];
__device__ __align__(128) __nv_bfloat16 g_WcombT_hi[NLAYERS * 384 * 256];
__device__ __align__(128) __nv_bfloat16 g_WcombT_lo[NLAYERS * 384 * 256];
__device__ __align__(128) __nv_bfloat16 g_WoutT_hi [NLAYERS * 256 * 256];
__device__ __align__(128) __nv_bfloat16 g_WoutT_lo [NLAYERS * 256 * 256];
__device__ __align__(128) __nv_bfloat16 g_W1T_hi   [NLAYERS * 1024 * 256];
__device__ __align__(128) __nv_bfloat16 g_W1T_lo   [NLAYERS * 1024 * 256];
__device__ __align__(128) __nv_bfloat16 g_W2T_hi   [NLAYERS * 256 * 1024];
__device__ __align__(128) __nv_bfloat16 g_W2T_lo   [NLAYERS * 256 * 1024];
__device__ __align__(128) float g_bcomb[NLAYERS * 384];

// ---------------------------------------------------------------------------
// helpers
// ---------------------------------------------------------------------------
__device__ __forceinline__ uint32_t smem_u32(const void* p) {
    uint32_t a;
    asm("{ .reg .u64 t; cvta.to.shared.u64 t, %1; cvt.u32.u64 %0, t; }" : "=r"(a) : "l"(p));
    return a;
}
__device__ __forceinline__ void level_of_s(int s, int& lvl, int& start, int& hh, int& ww) {
    if (s < 16384)      { lvl = 0; start = 0;     hh = 128; ww = 128; }
    else if (s < 20480) { lvl = 1; start = 16384; hh = 64;  ww = 64;  }
    else if (s < 21504) { lvl = 2; start = 20480; hh = 32;  ww = 32;  }
    else                { lvl = 3; start = 21504; hh = 16;  ww = 16;  }
}
__device__ __forceinline__ void split_bf16(float v, __nv_bfloat16& h, __nv_bfloat16& l) {
    h = __float2bfloat16(v);
    l = __float2bfloat16(v - __bfloat162float(h));
}

// ---------------------------------------------------------------------------
// Fused weight preprocessing (one launch)
// ---------------------------------------------------------------------------
#define PER_LAYER_W 753664
__global__ void wsplit_all_kernel(const float* __restrict__ Wval, const float* __restrict__ Woff,
                                  const float* __restrict__ Wattn, const float* __restrict__ Wout,
                                  const float* __restrict__ W1, const float* __restrict__ W2) {
    unsigned idx = blockIdx.x * blockDim.x + threadIdx.x;
    unsigned total = NLAYERS * PER_LAYER_W;
    if (idx >= total) return;
    unsigned layer = idx / PER_LAYER_W;
    unsigned r = idx - layer * PER_LAYER_W;

    float a;
    __nv_bfloat16 *hi, *lo;
    size_t dst;
    if (r < 65536u) {
        unsigned t = r, n = t >> 8, k = t & 255;
        a = Wval[(size_t)layer * 65536 + k * 256 + n];
        hi = g_WvalT_hi; lo = g_WvalT_lo; dst = (size_t)layer * 65536 + t;
    } else if (r < 131072u) {
        unsigned t = r - 65536u, n = t >> 8, k = t & 255;
        a = Woff[(size_t)layer * 65536 + k * 256 + n];
        hi = g_WcombT_hi; lo = g_WcombT_lo; dst = (size_t)layer * 98304 + t;
    } else if (r < 163840u) {
        unsigned t = r - 131072u, n = t >> 8, k = t & 255;
        a = Wattn[(size_t)layer * 32768 + k * 128 + n];
        hi = g_WcombT_hi; lo = g_WcombT_lo; dst = (size_t)layer * 98304 + 65536 + t;
    } else if (r < 229376u) {
        unsigned t = r - 163840u, n = t >> 8, k = t & 255;
        a = Wout[(size_t)layer * 65536 + k * 256 + n];
        hi = g_WoutT_hi; lo = g_WoutT_lo; dst = (size_t)layer * 65536 + t;
    } else if (r < 491520u) {
        unsigned t = r - 229376u, n = t >> 8, k = t & 255;
        a = W1[(size_t)layer * 262144 + k * 1024 + n];
        hi = g_W1T_hi; lo = g_W1T_lo; dst = (size_t)layer * 262144 + t;
    } else {
        unsigned t = r - 491520u, n = t >> 10, k = t & 1023;
        a = W2[(size_t)layer * 262144 + k * 256 + n];
        hi = g_W2T_hi; lo = g_W2T_lo; dst = (size_t)layer * 262144 + t;
    }
    __nv_bfloat16 h, l;
    split_bf16(a, h, l);
    hi[dst] = h; lo[dst] = l;
}

__global__ void bcomb_kernel(const float* __restrict__ boff, const float* __restrict__ battn) {
    int i = blockIdx.x * blockDim.x + threadIdx.x;
    if (i >= NLAYERS * 384) return;
    int l = i / 384, c = i % 384;
    g_bcomb[i] = (c < 256) ? boff[l * 256 + c] : battn[l * 128 + (c - 256)];
}

// ---------------------------------------------------------------------------
// Flatten
// ---------------------------------------------------------------------------
__global__ void flatten_kernel(const float* __restrict__ s0, const float* __restrict__ s1,
                               const float* __restrict__ s2, const float* __restrict__ s3,
                               const float* __restrict__ p0, const float* __restrict__ p1,
                               const float* __restrict__ p2, const float* __restrict__ p3,
                               const float* __restrict__ le) {
    size_t idx = (size_t)blockIdx.x * blockDim.x + threadIdx.x;
    size_t total = (size_t)M_ROWS * D;
    if (idx >= total) return;
    int d = (int)(idx % D);
    int bs = (int)(idx / D);
    int s = bs % S_TOTAL;
    int b = bs / S_TOTAL;
    int lvl, start, hh, ww;
    level_of_s(s, lvl, start, hh, ww);
    int local = s - start;
    int y = local / ww;
    int x = local % ww;
    const float* sp; const float* pp;
    switch (lvl) {
        case 0: sp = s0; pp = p0; break;
        case 1: sp = s1; pp = p1; break;
        case 2: sp = s2; pp = p2; break;
        default: sp = s3; pp = p3; break;
    }
    size_t off = (((size_t)b * D + d) * hh + y) * ww + x;
    float ov = sp[off];
    float pv = pp[off] + le[lvl * D + d];
    g_out[idx] = ov;
    g_pos[idx] = pv;
    __nv_bfloat16 h, l;
    split_bf16(ov, h, l);
    g_out_hi[idx] = h; g_out_lo[idx] = l;
    split_bf16(ov + pv, h, l);
    g_q_hi[idx] = h; g_q_lo[idx] = l;
}

// ---------------------------------------------------------------------------
// Tensor-core GEMM, mma.sync bf16 3-term, 3-stage cp.async pipeline.
// BM=BN=128, BK=32; 256 threads = 8 warps (2m x 4n).
// OUT: 0=f32, 1=bf16 hi/lo, 2=fp16
// ---------------------------------------------------------------------------
#define GM_STAGE 32768
#define GM_SMEM (3 * GM_STAGE)

__device__ __forceinline__ uint32_t swz(int row, int g) {
    return (uint32_t)(row * 64) + (uint32_t)((g ^ ((row >> 1) & 3)) << 4);
}

template <bool RELU, int OUT>
__global__ void __launch_bounds__(256)
gemm_mma(const __nv_bfloat16* __restrict__ Ahi, const __nv_bfloat16* __restrict__ Alo,
         const __nv_bfloat16* __restrict__ Bhi, const __nv_bfloat16* __restrict__ Blo,
         const float* __restrict__ bias,
         float* __restrict__ Cf, __nv_bfloat16* __restrict__ Chi, __nv_bfloat16* __restrict__ Clo,
         __half* __restrict__ Ch,
         int N, int K) {
    extern __shared__ char smem[];
    const uint32_t sb = smem_u32(smem);
    const int tid = threadIdx.x;
    const int lane = tid & 31;
    const int wid = tid >> 5;
    const int bm = blockIdx.y * 128;
    const int bn = blockIdx.x * 128;
    const int wm = (wid >> 2) * 64;
    const int wn = (wid & 3) * 32;
    const int nk = K >> 5;

    float acc[4][4][4];
    #pragma unroll
    for (int i = 0; i < 4; ++i)
        #pragma unroll
        for (int j = 0; j < 4; ++j)
            #pragma unroll
            for (int r = 0; r < 4; ++r) acc[i][j][r] = 0.f;

    auto issue = [&](int st, int kt) {
        uint32_t base = sb + (uint32_t)st * GM_STAGE;
        #pragma unroll
        for (int t = 0; t < 2; ++t) {
            int j = tid + t * 256;
            int row = j >> 2, gc = j & 3;
            uint32_t off = swz(row, gc);
            size_t ak = (size_t)(bm + row) * K + kt * 32 + gc * 8;
            size_t bk = (size_t)(bn + row) * K + kt * 32 + gc * 8;
            asm volatile("cp.async.cg.shared.global [%0], [%1], 16;" :: "r"(base + off),          "l"(Ahi + ak));
            asm volatile("cp.async.cg.shared.global [%0], [%1], 16;" :: "r"(base + 8192u + off),  "l"(Alo + ak));
            asm volatile("cp.async.cg.shared.global [%0], [%1], 16;" :: "r"(base + 16384u + off), "l"(Bhi + bk));
            asm volatile("cp.async.cg.shared.global [%0], [%1], 16;" :: "r"(base + 24576u + off), "l"(Blo + bk));
        }
        asm volatile("cp.async.commit_group;");
    };

    // prologue: 2 stages in flight
    issue(0, 0);
    if (nk > 1) issue(1, 1);

    for (int kt = 0; kt < nk; ++kt) {
        if (kt + 1 < nk) asm volatile("cp.async.wait_group 1;");
        else             asm volatile("cp.async.wait_group 0;");
        __syncthreads();
        if (kt + 2 < nk) issue((kt + 2) % 3, kt + 2);

        uint32_t base = sb + (uint32_t)(kt % 3) * GM_STAGE;
        #pragma unroll
        for (int ks = 0; ks < 2; ++ks) {
            uint32_t ah[4][4], al[4][4], bh[4][2], bl[4][2];
            #pragma unroll
            for (int im = 0; im < 4; ++im) {
                int r = wm + im * 16 + (lane & 15);
                int g = (ks << 1) + (lane >> 4);
                uint32_t adr = base + swz(r, g);
                asm volatile("ldmatrix.sync.aligned.m8n8.x4.shared.b16 {%0,%1,%2,%3}, [%4];"
                             : "=r"(ah[im][0]), "=r"(ah[im][1]), "=r"(ah[im][2]), "=r"(ah[im][3]) : "r"(adr));
                asm volatile("ldmatrix.sync.aligned.m8n8.x4.shared.b16 {%0,%1,%2,%3}, [%4];"
                             : "=r"(al[im][0]), "=r"(al[im][1]), "=r"(al[im][2]), "=r"(al[im][3]) : "r"(adr + 8192u));
            }
            #pragma unroll
            for (int in = 0; in < 4; ++in) {
                int r = wn + in * 8 + (lane & 7);
                int g = (ks << 1) + ((lane >> 3) & 1);
                uint32_t adr = base + 16384u + swz(r, g);
                asm volatile("ldmatrix.sync.aligned.m8n8.x2.shared.b16 {%0,%1}, [%2];"
                             : "=r"(bh[in][0]), "=r"(bh[in][1]) : "r"(adr));
                asm volatile("ldmatrix.sync.aligned.m8n8.x2.shared.b16 {%0,%1}, [%2];"
                             : "=r"(bl[in][0]), "=r"(bl[in][1]) : "r"(adr + 8192u));
            }
            #pragma unroll
            for (int im = 0; im < 4; ++im) {
                #pragma unroll
                for (int in = 0; in < 4; ++in) {
                    float* c = acc[im][in];
                    asm volatile("mma.sync.aligned.m16n8k16.row.col.f32.bf16.bf16.f32 "
                                 "{%0,%1,%2,%3},{%4,%5,%6,%7},{%8,%9},{%0,%1,%2,%3};"
                                 : "+f"(c[0]), "+f"(c[1]), "+f"(c[2]), "+f"(c[3])
                                 : "r"(ah[im][0]), "r"(ah[im][1]), "r"(ah[im][2]), "r"(ah[im][3]),
                                   "r"(bh[in][0]), "r"(bh[in][1]));
                    asm volatile("mma.sync.aligned.m16n8k16.row.col.f32.bf16.bf16.f32 "
                                 "{%0,%1,%2,%3},{%4,%5,%6,%7},{%8,%9},{%0,%1,%2,%3};"
                                 : "+f"(c[0]), "+f"(c[1]), "+f"(c[2]), "+f"(c[3])
                                 : "r"(ah[im][0]), "r"(ah[im][1]), "r"(ah[im][2]), "r"(ah[im][3]),
                                   "r"(bl[in][0]), "r"(bl[in][1]));
                    asm volatile("mma.sync.aligned.m16n8k16.row.col.f32.bf16.bf16.f32 "
                                 "{%0,%1,%2,%3},{%4,%5,%6,%7},{%8,%9},{%0,%1,%2,%3};"
                                 : "+f"(c[0]), "+f"(c[1]), "+f"(c[2]), "+f"(c[3])
                                 : "r"(al[im][0]), "r"(al[im][1]), "r"(al[im][2]), "r"(al[im][3]),
                                   "r"(bh[in][0]), "r"(bh[in][1]));
                }
            }
        }
    }

    const int r0 = bm + wm + (lane >> 2);
    const int c0 = bn + wn + (lane & 3) * 2;
    #pragma unroll
    for (int im = 0; im < 4; ++im) {
        #pragma unroll
        for (int in = 0; in < 4; ++in) {
            int r = r0 + im * 16;
            int c = c0 + in * 8;
            float b0 = bias[c], b1 = bias[c + 1];
            float v0 = acc[im][in][0] + b0;
            float v1 = acc[im][in][1] + b1;
            float v2 = acc[im][in][2] + b0;
            float v3 = acc[im][in][3] + b1;
            if (RELU) {
                v0 = fmaxf(v0, 0.f); v1 = fmaxf(v1, 0.f);
                v2 = fmaxf(v2, 0.f); v3 = fmaxf(v3, 0.f);
            }
            if (OUT == 1) {
                __nv_bfloat16 h0, l0, h1, l1;
                split_bf16(v0, h0, l0); split_bf16(v1, h1, l1);
                uint32_t ph = (uint32_t)__bfloat16_as_ushort(h0) | ((uint32_t)__bfloat16_as_ushort(h1) << 16);
                uint32_t pl = (uint32_t)__bfloat16_as_ushort(l0) | ((uint32_t)__bfloat16_as_ushort(l1) << 16);
                *reinterpret_cast<uint32_t*>(Chi + (size_t)r * N + c) = ph;
                *reinterpret_cast<uint32_t*>(Clo + (size_t)r * N + c) = pl;
                split_bf16(v2, h0, l0); split_bf16(v3, h1, l1);
                ph = (uint32_t)__bfloat16_as_ushort(h0) | ((uint32_t)__bfloat16_as_ushort(h1) << 16);
                pl = (uint32_t)__bfloat16_as_ushort(l0) | ((uint32_t)__bfloat16_as_ushort(l1) << 16);
                *reinterpret_cast<uint32_t*>(Chi + (size_t)(r + 8) * N + c) = ph;
                *reinterpret_cast<uint32_t*>(Clo + (size_t)(r + 8) * N + c) = pl;
            } else if (OUT == 2) {
                *reinterpret_cast<__half2*>(Ch + (size_t)r * N + c) = __floats2half2_rn(v0, v1);
                *reinterpret_cast<__half2*>(Ch + (size_t)(r + 8) * N + c) = __floats2half2_rn(v2, v3);
            } else {
                *reinterpret_cast<float2*>(Cf + (size_t)r * N + c) = make_float2(v0, v1);
                *reinterpret_cast<float2*>(Cf + (size_t)(r + 8) * N + c) = make_float2(v2, v3);
            }
        }
    }
}

// ---------------------------------------------------------------------------
// MS-deform sampling, fused softmax, BRANCHLESS gathers.
// warp per (b,s,h), lane = channel.
// ---------------------------------------------------------------------------
__global__ __launch_bounds__(256)
void sample_kernel() {
    int warp = (blockIdx.x * blockDim.x + threadIdx.x) >> 5;
    int lane = threadIdx.x & 31;
    if (warp >= M_ROWS * NH) return;
    int h = warp & 7;
    int bs = warp >> 3;
    int b = bs / S_TOTAL;
    int s = bs - b * S_TOTAL;

    // fused softmax over 16 logits (lanes 0-15 own one each)
    const float* logit_p = g_offattn + (size_t)bs * 384 + 256 + h * 16;
    float lg = (lane < 16) ? logit_p[lane] : -1e30f;
    float mx = lg;
    #pragma unroll
    for (int o = 8; o > 0; o >>= 1) mx = fmaxf(mx, __shfl_xor_sync(0xffffffffu, mx, o));
    float e = (lane < 16) ? expf(lg - mx) : 0.f;
    float sm = e;
    #pragma unroll
    for (int o = 8; o > 0; o >>= 1) sm += __shfl_xor_sync(0xffffffffu, sm, o);
    float aw_lane = e / sm;

    // offsets: 32 floats, one per lane
    float off_lane = g_offattn[(size_t)bs * 384 + h * 32 + lane];

    int qlvl, qstart, qh, qw;
    level_of_s(s, qlvl, qstart, qh, qw);
    int qlocal = s - qstart;
    int qy = qlocal / qw;
    int qx = qlocal - qy * qw;
    float ref_x = (qx + 0.5f) / (float)qw;
    float ref_y = (qy + 0.5f) / (float)qh;

    const __half* valb = g_value + (size_t)b * S_TOTAL * D + h * DH + lane;

    float acc = 0.f;
    #pragma unroll
    for (int l = 0; l < NL; ++l) {
        const int W = c_lvl_w[l], H = c_lvl_h[l], start = c_lvl_start[l];
        const float fW = (float)W, fH = (float)H;
        #pragma unroll
        for (int p = 0; p < NP; ++p) {
            float ox = __shfl_sync(0xffffffffu, off_lane, l * 8 + p * 2 + 0);
            float oy = __shfl_sync(0xffffffffu, off_lane, l * 8 + p * 2 + 1);
            float aw = __shfl_sync(0xffffffffu, aw_lane, l * 4 + p);
            float x = (ref_x + ox / fW) * fW - 0.5f;
            float y = (ref_y + oy / fH) * fH - 0.5f;
            float x0f = floorf(x), y0f = floorf(y);
            float lx = x - x0f, ly = y - y0f;
            int x0 = (int)x0f, y0 = (int)y0f;
            int x1 = x0 + 1, y1 = y0 + 1;
            // validity masks as floats
            float mx0 = (x0 >= 0 && x0 < W) ? 1.f : 0.f;
            float mx1 = (x1 >= 0 && x1 < W) ? 1.f : 0.f;
            float my0 = (y0 >= 0 && y0 < H) ? 1.f : 0.f;
            float my1 = (y1 >= 0 && y1 < H) ? 1.f : 0.f;
            // clamped indices (always in-bounds)
            int cx0 = min(max(x0, 0), W - 1);
            int cx1 = min(max(x1, 0), W - 1);
            int cy0 = min(max(y0, 0), H - 1);
            int cy1 = min(max(y1, 0), H - 1);
            int i00 = start + cy0 * W + cx0;
            int i10 = start + cy0 * W + cx1;
            int i01 = start + cy1 * W + cx0;
            int i11 = start + cy1 * W + cx1;
            // unconditional loads
            float v00 = __half2float(valb[(size_t)i00 * D]);
            float v10 = __half2float(valb[(size_t)i10 * D]);
            float v01 = __half2float(valb[(size_t)i01 * D]);
            float v11 = __half2float(valb[(size_t)i11 * D]);
            float w00 = (1.f - lx) * (1.f - ly) * mx0 * my0;
            float w10 = lx * (1.f - ly) * mx1 * my0;
            float w01 = (1.f - lx) * ly * mx0 * my1;
            float w11 = lx * ly * mx1 * my1;
            float samp = w00 * v00 + w10 * v10 + w01 * v01 + w11 * v11;
            acc = fmaf(aw, samp, acc);
        }
    }
    size_t oidx = (size_t)bs * D + h * DH + lane;
    __nv_bfloat16 hh, ll;
    split_bf16(acc, hh, ll);
    g_attn_hi[oidx] = hh;
    g_attn_lo[oidx] = ll;
}

// ---------------------------------------------------------------------------
// dst = LayerNorm(x + y); optional bf16 hi/lo; optional q=dst+pos hi/lo
// ---------------------------------------------------------------------------
__global__ __launch_bounds__(256)
void residual_ln_kernel(const float* __restrict__ x, const float* __restrict__ y,
                        const float* __restrict__ gamma, const float* __restrict__ beta,
                        float* __restrict__ dst,
                        __nv_bfloat16* __restrict__ dhi, __nv_bfloat16* __restrict__ dlo,
                        const float* __restrict__ pos,
                        __nv_bfloat16* __restrict__ qhi, __nv_bfloat16* __restrict__ qlo) {
    int row = (blockIdx.x * blockDim.x + threadIdx.x) >> 5;
    int lane = threadIdx.x & 31;
    if (row >= M_ROWS) return;
    const float* xr = x + (size_t)row * D + lane * 8;
    const float* yr = y + (size_t)row * D + lane * 8;
    float v[8];
    float s = 0.f;
    #pragma unroll
    for (int i = 0; i < 8; ++i) { v[i] = xr[i] + yr[i]; s += v[i]; }
    #pragma unroll
    for (int o = 16; o > 0; o >>= 1) s += __shfl_xor_sync(0xffffffffu, s, o);
    float mean = s * (1.f / D);
    float vs = 0.f;
    #pragma unroll
    for (int i = 0; i < 8; ++i) { float d = v[i] - mean; vs += d * d; }
    #pragma unroll
    for (int o = 16; o > 0; o >>= 1) vs += __shfl_xor_sync(0xffffffffu, vs, o);
    float rstd = rsqrtf(vs * (1.f / D) + 1e-5f);

    size_t base = (size_t)row * D + lane * 8;
    float* dr = dst + base;
    float w[8];
    #pragma unroll
    for (int i = 0; i < 8; ++i) {
        int c = lane * 8 + i;
        w[i] = (v[i] - mean) * rstd * gamma[c] + beta[c];
        dr[i] = w[i];
    }
    if (dhi) {
        uint32_t ph[4], pl[4];
        #pragma unroll
        for (int p = 0; p < 4; ++p) {
            __nv_bfloat16 h0, l0, h1, l1;
            split_bf16(w[2 * p], h0, l0);
            split_bf16(w[2 * p + 1], h1, l1);
            ph[p] = (uint32_t)__bfloat16_as_ushort(h0) | ((uint32_t)__bfloat16_as_ushort(h1) << 16);
            pl[p] = (uint32_t)__bfloat16_as_ushort(l0) | ((uint32_t)__bfloat16_as_ushort(l1) << 16);
        }
        *reinterpret_cast<uint4*>(dhi + base) = make_uint4(ph[0], ph[1], ph[2], ph[3]);
        *reinterpret_cast<uint4*>(dlo + base) = make_uint4(pl[0], pl[1], pl[2], pl[3]);
    }
    if (qhi) {
        const float* pr = pos + base;
        uint32_t ph[4], pl[4];
        #pragma unroll
        for (int p = 0; p < 4; ++p) {
            __nv_bfloat16 h0, l0, h1, l1;
            split_bf16(w[2 * p] + pr[2 * p], h0, l0);
            split_bf16(w[2 * p + 1] + pr[2 * p + 1], h1, l1);
            ph[p] = (uint32_t)__bfloat16_as_ushort(h0) | ((uint32_t)__bfloat16_as_ushort(h1) << 16);
            pl[p] = (uint32_t)__bfloat16_as_ushort(l0) | ((uint32_t)__bfloat16_as_ushort(l1) << 16);
        }
        *reinterpret_cast<uint4*>(qhi + base) = make_uint4(ph[0], ph[1], ph[2], ph[3]);
        *reinterpret_cast<uint4*>(qlo + base) = make_uint4(pl[0], pl[1], pl[2], pl[3]);
    }
}

// ---------------------------------------------------------------------------
// host launcher
// ---------------------------------------------------------------------------
extern "C" void kernel_launch(void* const* d_in, const int* in_sizes, int n_in,
                              void* d_out, int out_size) {
    const int lvl_elems[NL] = {
        BATCH * D * 128 * 128, BATCH * D * 64 * 64,
        BATCH * D * 32 * 32,   BATCH * D * 16 * 16
    };
    const float* srcp[NL] = {0, 0, 0, 0};
    const float* posp[NL] = {0, 0, 0, 0};
    for (int i = 0; i < 8; ++i) {
        int sz = in_sizes[i];
        for (int l = 0; l < NL; ++l) {
            if (sz == lvl_elems[l]) {
                if (!srcp[l]) srcp[l] = (const float*)d_in[i];
                else if (!posp[l]) posp[l] = (const float*)d_in[i];
                break;
            }
        }
    }

    const float* level_embed = (const float*)d_in[8];
    const float* Woff  = (const float*)d_in[9];
    const float* boff  = (const float*)d_in[10];
    const float* Wattn = (const float*)d_in[11];
    const float* battn = (const float*)d_in[12];
    const float* Wval  = (const float*)d_in[13];
    const float* bval  = (const float*)d_in[14];
    const float* Wout  = (const float*)d_in[15];
    const float* bout  = (const float*)d_in[16];
    const float* ln1_s = (const float*)d_in[17];
    const float* ln1_b = (const float*)d_in[18];
    const float* W1    = (const float*)d_in[19];
    const float* b1    = (const float*)d_in[20];
    const float* W2    = (const float*)d_in[21];
    const float* b2    = (const float*)d_in[22];
    const float* ln2_s = (const float*)d_in[23];
    const float* ln2_b = (const float*)d_in[24];
    float* out = (float*)d_out;

    float *p_pos, *p_out, *p_offattn, *p_proj, *p_ffn2, *p_bcomb;
    __half* p_value;
    __nv_bfloat16 *p_out_hi, *p_out_lo, *p_q_hi, *p_q_lo, *p_ln1_hi, *p_ln1_lo,
                  *p_attn_hi, *p_attn_lo, *p_f1_hi, *p_f1_lo;
    __nv_bfloat16 *p_WvalT_hi, *p_WvalT_lo, *p_WcombT_hi, *p_WcombT_lo,
                  *p_WoutT_hi, *p_WoutT_lo, *p_W1T_hi, *p_W1T_lo, *p_W2T_hi, *p_W2T_lo;
    cudaGetSymbolAddress((void**)&p_pos, g_pos);
    cudaGetSymbolAddress((void**)&p_out, g_out);
    cudaGetSymbolAddress((void**)&p_value, g_value);
    cudaGetSymbolAddress((void**)&p_offattn, g_offattn);
    cudaGetSymbolAddress((void**)&p_proj, g_proj);
    cudaGetSymbolAddress((void**)&p_ffn2, g_ffn2);
    cudaGetSymbolAddress((void**)&p_bcomb, g_bcomb);
    cudaGetSymbolAddress((void**)&p_out_hi, g_out_hi);
    cudaGetSymbolAddress((void**)&p_out_lo, g_out_lo);
    cudaGetSymbolAddress((void**)&p_q_hi, g_q_hi);
    cudaGetSymbolAddress((void**)&p_q_lo, g_q_lo);
    cudaGetSymbolAddress((void**)&p_ln1_hi, g_ln1_hi);
    cudaGetSymbolAddress((void**)&p_ln1_lo, g_ln1_lo);
    cudaGetSymbolAddress((void**)&p_attn_hi, g_attn_hi);
    cudaGetSymbolAddress((void**)&p_attn_lo, g_attn_lo);
    cudaGetSymbolAddress((void**)&p_f1_hi, g_f1_hi);
    cudaGetSymbolAddress((void**)&p_f1_lo, g_f1_lo);
    cudaGetSymbolAddress((void**)&p_WvalT_hi, g_WvalT_hi);
    cudaGetSymbolAddress((void**)&p_WvalT_lo, g_WvalT_lo);
    cudaGetSymbolAddress((void**)&p_WcombT_hi, g_WcombT_hi);
    cudaGetSymbolAddress((void**)&p_WcombT_lo, g_WcombT_lo);
    cudaGetSymbolAddress((void**)&p_WoutT_hi, g_WoutT_hi);
    cudaGetSymbolAddress((void**)&p_WoutT_lo, g_WoutT_lo);
    cudaGetSymbolAddress((void**)&p_W1T_hi, g_W1T_hi);
    cudaGetSymbolAddress((void**)&p_W1T_lo, g_W1T_lo);
    cudaGetSymbolAddress((void**)&p_W2T_hi, g_W2T_hi);
    cudaGetSymbolAddress((void**)&p_W2T_lo, g_W2T_lo);

    cudaFuncSetAttribute(gemm_mma<false, 0>, cudaFuncAttributeMaxDynamicSharedMemorySize, GM_SMEM);
    cudaFuncSetAttribute(gemm_mma<false, 2>, cudaFuncAttributeMaxDynamicSharedMemorySize, GM_SMEM);
    cudaFuncSetAttribute(gemm_mma<true, 1>,  cudaFuncAttributeMaxDynamicSharedMemorySize, GM_SMEM);

    const int TB = 256;
    const size_t total = (size_t)M_ROWS * D;
    const int elem_blocks = (int)((total + TB - 1) / TB);

    {
        unsigned n = NLAYERS * PER_LAYER_W;
        wsplit_all_kernel<<<(n + 255) / 256, 256>>>(Wval, Woff, Wattn, Wout, W1, W2);
        bcomb_kernel<<<(NLAYERS * 384 + 255) / 256, 256>>>(boff, battn);
    }

    flatten_kernel<<<elem_blocks, TB>>>(srcp[0], srcp[1], srcp[2], srcp[3],
                                        posp[0], posp[1], posp[2], posp[3], level_embed);

    const dim3 gblk(256);
    for (int i = 0; i < NLAYERS; ++i) {
        // value = out @ Wval + bval -> fp16
        gemm_mma<false, 2><<<dim3(2, M_ROWS / 128), gblk, GM_SMEM>>>(
            p_out_hi, p_out_lo,
            p_WvalT_hi + (size_t)i * 256 * 256, p_WvalT_lo + (size_t)i * 256 * 256,
            bval + (size_t)i * 256, 0, 0, 0, p_value, 256, 256);
        // [off | attn logits] = q @ Wcomb + bcomb
        gemm_mma<false, 0><<<dim3(3, M_ROWS / 128), gblk, GM_SMEM>>>(
            p_q_hi, p_q_lo,
            p_WcombT_hi + (size_t)i * 384 * 256, p_WcombT_lo + (size_t)i * 384 * 256,
            p_bcomb + (size_t)i * 384, p_offattn, 0, 0, 0, 384, 256);
        // deform sampling (softmax fused) -> attn hi/lo
        sample_kernel<<<(M_ROWS * NH * 32 + TB - 1) / TB, TB>>>();
        // proj = attnout @ Wout + bout
        gemm_mma<false, 0><<<dim3(2, M_ROWS / 128), gblk, GM_SMEM>>>(
            p_attn_hi, p_attn_lo,
            p_WoutT_hi + (size_t)i * 256 * 256, p_WoutT_lo + (size_t)i * 256 * 256,
            bout + (size_t)i * 256, p_proj, 0, 0, 0, 256, 256);
        // out = LN(out + proj), + ln1 hi/lo
        residual_ln_kernel<<<(M_ROWS * 32 + TB - 1) / TB, TB>>>(
            p_out, p_proj, ln1_s + (size_t)i * 256, ln1_b + (size_t)i * 256,
            p_out, p_ln1_hi, p_ln1_lo, (const float*)0, (__nv_bfloat16*)0, (__nv_bfloat16*)0);
        // ffn1 = relu(ln1 @ W1 + b1) -> bf16 hi/lo
        gemm_mma<true, 1><<<dim3(8, M_ROWS / 128), gblk, GM_SMEM>>>(
            p_ln1_hi, p_ln1_lo,
            p_W1T_hi + (size_t)i * 1024 * 256, p_W1T_lo + (size_t)i * 1024 * 256,
            b1 + (size_t)i * 1024, 0, p_f1_hi, p_f1_lo, 0, 1024, 256);
        // ffn2 = ffn1 @ W2 + b2
        gemm_mma<false, 0><<<dim3(2, M_ROWS / 128), gblk, GM_SMEM>>>(
            p_f1_hi, p_f1_lo,
            p_W2T_hi + (size_t)i * 256 * 1024, p_W2T_lo + (size_t)i * 256 * 1024,
            b2 + (size_t)i * 256, p_ffn2, 0, 0, 0, 256, 1024);
        // out = LN(out + ffn2)
        if (i == NLAYERS - 1) {
            residual_ln_kernel<<<(M_ROWS * 32 + TB - 1) / TB, TB>>>(
                p_out, p_ffn2, ln2_s + (size_t)i * 256, ln2_b + (size_t)i * 256,
                out, (__nv_bfloat16*)0, (__nv_bfloat16*)0,
                (const float*)0, (__nv_bfloat16*)0, (__nv_bfloat16*)0);
        } else {
            residual_ln_kernel<<<(M_ROWS * 32 + TB - 1) / TB, TB>>>(
                p_out, p_ffn2, ln2_s + (size_t)i * 256, ln2_b + (size_t)i * 256,
                p_out, p_out_hi, p_out_lo, p_pos, p_q_hi, p_q_lo);
        }
    }
}

// round 7
// speedup vs baseline: 1.3661x; 1.3661x over previous
#include <cuda_runtime.h>
#include <cuda_bf16.h>
#include <cuda_fp16.h>
#include <stdint.h>
#include <math.h>

#define BATCH 2
#define D 256
#define NH 8
#define DH 32
#define NL 4
#define NP 4
#define NLAYERS 6
#define DFF 1024
#define S_TOTAL 21760
#define M_ROWS (BATCH * S_TOTAL)   // 43520

__device__ __constant__ int c_lvl_h[NL]     = {128, 64, 32, 16};
__device__ __constant__ int c_lvl_w[NL]     = {128, 64, 32, 16};
__device__ __constant__ int c_lvl_start[NL] = {0, 16384, 20480, 21504};

// ---------------------------------------------------------------------------
// Scratch
// ---------------------------------------------------------------------------
__device__ __align__(128) float g_pos    [(size_t)M_ROWS * D];
__device__ __align__(128) float g_out    [(size_t)M_ROWS * D];
__device__ __align__(128) __half g_value [(size_t)M_ROWS * D];
__device__ __align__(128) float g_offattn[(size_t)M_ROWS * 384];
__device__ __align__(128) float g_proj   [(size_t)M_ROWS * D];
__device__ __align__(128) float g_ffn2   [(size_t)M_ROWS * D];

__device__ __align__(128) __nv_bfloat16 g_out_hi [(size_t)M_ROWS * D];
__device__ __align__(128) __nv_bfloat16 g_out_lo [(size_t)M_ROWS * D];
__device__ __align__(128) __nv_bfloat16 g_q_hi   [(size_t)M_ROWS * D];
__device__ __align__(128) __nv_bfloat16 g_q_lo   [(size_t)M_ROWS * D];
__device__ __align__(128) __nv_bfloat16 g_ln1_hi [(size_t)M_ROWS * D];
__device__ __align__(128) __nv_bfloat16 g_ln1_lo [(size_t)M_ROWS * D];
__device__ __align__(128) __nv_bfloat16 g_attn_hi[(size_t)M_ROWS * D];
__device__ __align__(128) __nv_bfloat16 g_attn_lo[(size_t)M_ROWS * D];
__device__ __align__(128) __nv_bfloat16 g_f1_hi  [(size_t)M_ROWS * DFF];
__device__ __align__(128) __nv_bfloat16 g_f1_lo  [(size_t)M_ROWS * DFF];

__device__ __align__(128) __nv_bfloat16 g_WvalT_hi [NLAYERS * 256 * 256];
__device__ __align__(128) __nv_bfloat16 g_WvalT_lo [NLAYERS * 256 * 256];
__device__ __align__(128) __nv_bfloat16 g_WcombT_hi[NLAYERS * 384 * 256];
__device__ __align__(128) __nv_bfloat16 g_WcombT_lo[NLAYERS * 384 * 256];
__device__ __align__(128) __nv_bfloat16 g_WoutT_hi [NLAYERS * 256 * 256];
__device__ __align__(128) __nv_bfloat16 g_WoutT_lo [NLAYERS * 256 * 256];
__device__ __align__(128) __nv_bfloat16 g_W1T_hi   [NLAYERS * 1024 * 256];
__device__ __align__(128) __nv_bfloat16 g_W1T_lo   [NLAYERS * 1024 * 256];
__device__ __align__(128) __nv_bfloat16 g_W2T_hi   [NLAYERS * 256 * 1024];
__device__ __align__(128) __nv_bfloat16 g_W2T_lo   [NLAYERS * 256 * 1024];
__device__ __align__(128) float g_bcomb[NLAYERS * 384];

// ---------------------------------------------------------------------------
// helpers
// ---------------------------------------------------------------------------
__device__ __forceinline__ uint32_t smem_u32(const void* p) {
    uint32_t a;
    asm("{ .reg .u64 t; cvta.to.shared.u64 t, %1; cvt.u32.u64 %0, t; }" : "=r"(a) : "l"(p));
    return a;
}
__device__ __forceinline__ void level_of_s(int s, int& lvl, int& start, int& hh, int& ww) {
    if (s < 16384)      { lvl = 0; start = 0;     hh = 128; ww = 128; }
    else if (s < 20480) { lvl = 1; start = 16384; hh = 64;  ww = 64;  }
    else if (s < 21504) { lvl = 2; start = 20480; hh = 32;  ww = 32;  }
    else                { lvl = 3; start = 21504; hh = 16;  ww = 16;  }
}
__device__ __forceinline__ void split_bf16(float v, __nv_bfloat16& h, __nv_bfloat16& l) {
    h = __float2bfloat16(v);
    l = __float2bfloat16(v - __bfloat162float(h));
}

// ---------------------------------------------------------------------------
// Fused weight preprocessing (one launch)
// ---------------------------------------------------------------------------
#define PER_LAYER_W 753664
__global__ void wsplit_all_kernel(const float* __restrict__ Wval, const float* __restrict__ Woff,
                                  const float* __restrict__ Wattn, const float* __restrict__ Wout,
                                  const float* __restrict__ W1, const float* __restrict__ W2) {
    unsigned idx = blockIdx.x * blockDim.x + threadIdx.x;
    unsigned total = NLAYERS * PER_LAYER_W;
    if (idx >= total) return;
    unsigned layer = idx / PER_LAYER_W;
    unsigned r = idx - layer * PER_LAYER_W;

    float a;
    __nv_bfloat16 *hi, *lo;
    size_t dst;
    if (r < 65536u) {
        unsigned t = r, n = t >> 8, k = t & 255;
        a = Wval[(size_t)layer * 65536 + k * 256 + n];
        hi = g_WvalT_hi; lo = g_WvalT_lo; dst = (size_t)layer * 65536 + t;
    } else if (r < 131072u) {
        unsigned t = r - 65536u, n = t >> 8, k = t & 255;
        a = Woff[(size_t)layer * 65536 + k * 256 + n];
        hi = g_WcombT_hi; lo = g_WcombT_lo; dst = (size_t)layer * 98304 + t;
    } else if (r < 163840u) {
        unsigned t = r - 131072u, n = t >> 8, k = t & 255;
        a = Wattn[(size_t)layer * 32768 + k * 128 + n];
        hi = g_WcombT_hi; lo = g_WcombT_lo; dst = (size_t)layer * 98304 + 65536 + t;
    } else if (r < 229376u) {
        unsigned t = r - 163840u, n = t >> 8, k = t & 255;
        a = Wout[(size_t)layer * 65536 + k * 256 + n];
        hi = g_WoutT_hi; lo = g_WoutT_lo; dst = (size_t)layer * 65536 + t;
    } else if (r < 491520u) {
        unsigned t = r - 229376u, n = t >> 8, k = t & 255;
        a = W1[(size_t)layer * 262144 + k * 1024 + n];
        hi = g_W1T_hi; lo = g_W1T_lo; dst = (size_t)layer * 262144 + t;
    } else {
        unsigned t = r - 491520u, n = t >> 10, k = t & 1023;
        a = W2[(size_t)layer * 262144 + k * 256 + n];
        hi = g_W2T_hi; lo = g_W2T_lo; dst = (size_t)layer * 262144 + t;
    }
    __nv_bfloat16 h, l;
    split_bf16(a, h, l);
    hi[dst] = h; lo[dst] = l;
}

__global__ void bcomb_kernel(const float* __restrict__ boff, const float* __restrict__ battn) {
    int i = blockIdx.x * blockDim.x + threadIdx.x;
    if (i >= NLAYERS * 384) return;
    int l = i / 384, c = i % 384;
    g_bcomb[i] = (c < 256) ? boff[l * 256 + c] : battn[l * 128 + (c - 256)];
}

// ---------------------------------------------------------------------------
// Flatten
// ---------------------------------------------------------------------------
__global__ void flatten_kernel(const float* __restrict__ s0, const float* __restrict__ s1,
                               const float* __restrict__ s2, const float* __restrict__ s3,
                               const float* __restrict__ p0, const float* __restrict__ p1,
                               const float* __restrict__ p2, const float* __restrict__ p3,
                               const float* __restrict__ le) {
    size_t idx = (size_t)blockIdx.x * blockDim.x + threadIdx.x;
    size_t total = (size_t)M_ROWS * D;
    if (idx >= total) return;
    int d = (int)(idx % D);
    int bs = (int)(idx / D);
    int s = bs % S_TOTAL;
    int b = bs / S_TOTAL;
    int lvl, start, hh, ww;
    level_of_s(s, lvl, start, hh, ww);
    int local = s - start;
    int y = local / ww;
    int x = local % ww;
    const float* sp; const float* pp;
    switch (lvl) {
        case 0: sp = s0; pp = p0; break;
        case 1: sp = s1; pp = p1; break;
        case 2: sp = s2; pp = p2; break;
        default: sp = s3; pp = p3; break;
    }
    size_t off = (((size_t)b * D + d) * hh + y) * ww + x;
    float ov = sp[off];
    float pv = pp[off] + le[lvl * D + d];
    g_out[idx] = ov;
    g_pos[idx] = pv;
    __nv_bfloat16 h, l;
    split_bf16(ov, h, l);
    g_out_hi[idx] = h; g_out_lo[idx] = l;
    split_bf16(ov + pv, h, l);
    g_q_hi[idx] = h; g_q_lo[idx] = l;
}

// ---------------------------------------------------------------------------
// Tensor-core GEMM, mma.sync bf16 3-term, 2-stage cp.async (R4 proven config).
// BM=BN=128, BK=32; 256 threads = 8 warps (2m x 4n).
// OUT: 0=f32, 1=bf16 hi/lo, 2=fp16
// ---------------------------------------------------------------------------
#define GM_SMEM 65536

__device__ __forceinline__ uint32_t swz(int row, int g) {
    return (uint32_t)(row * 64) + (uint32_t)((g ^ ((row >> 1) & 3)) << 4);
}

template <bool RELU, int OUT>
__global__ void __launch_bounds__(256)
gemm_mma(const __nv_bfloat16* __restrict__ Ahi, const __nv_bfloat16* __restrict__ Alo,
         const __nv_bfloat16* __restrict__ Bhi, const __nv_bfloat16* __restrict__ Blo,
         const float* __restrict__ bias,
         float* __restrict__ Cf, __nv_bfloat16* __restrict__ Chi, __nv_bfloat16* __restrict__ Clo,
         __half* __restrict__ Ch,
         int N, int K) {
    extern __shared__ char smem[];
    const uint32_t sb = smem_u32(smem);
    const int tid = threadIdx.x;
    const int lane = tid & 31;
    const int wid = tid >> 5;
    const int bm = blockIdx.y * 128;
    const int bn = blockIdx.x * 128;
    const int wm = (wid >> 2) * 64;
    const int wn = (wid & 3) * 32;
    const int nk = K >> 5;

    float acc[4][4][4];
    #pragma unroll
    for (int i = 0; i < 4; ++i)
        #pragma unroll
        for (int j = 0; j < 4; ++j)
            #pragma unroll
            for (int r = 0; r < 4; ++r) acc[i][j][r] = 0.f;

    auto issue = [&](int st, int kt) {
        uint32_t base = sb + (uint32_t)st * 32768u;
        #pragma unroll
        for (int t = 0; t < 2; ++t) {
            int j = tid + t * 256;
            int row = j >> 2, gc = j & 3;
            uint32_t off = swz(row, gc);
            size_t ak = (size_t)(bm + row) * K + kt * 32 + gc * 8;
            size_t bk = (size_t)(bn + row) * K + kt * 32 + gc * 8;
            asm volatile("cp.async.cg.shared.global [%0], [%1], 16;" :: "r"(base + off),          "l"(Ahi + ak));
            asm volatile("cp.async.cg.shared.global [%0], [%1], 16;" :: "r"(base + 8192u + off),  "l"(Alo + ak));
            asm volatile("cp.async.cg.shared.global [%0], [%1], 16;" :: "r"(base + 16384u + off), "l"(Bhi + bk));
            asm volatile("cp.async.cg.shared.global [%0], [%1], 16;" :: "r"(base + 24576u + off), "l"(Blo + bk));
        }
        asm volatile("cp.async.commit_group;");
    };

    issue(0, 0);

    for (int kt = 0; kt < nk; ++kt) {
        const bool more = (kt + 1 < nk);
        if (more) issue((kt + 1) & 1, kt + 1);
        if (more) asm volatile("cp.async.wait_group 1;");
        else      asm volatile("cp.async.wait_group 0;");
        __syncthreads();

        uint32_t base = sb + (uint32_t)(kt & 1) * 32768u;
        #pragma unroll
        for (int ks = 0; ks < 2; ++ks) {
            uint32_t ah[4][4], al[4][4], bh[4][2], bl[4][2];
            #pragma unroll
            for (int im = 0; im < 4; ++im) {
                int r = wm + im * 16 + (lane & 15);
                int g = (ks << 1) + (lane >> 4);
                uint32_t adr = base + swz(r, g);
                asm volatile("ldmatrix.sync.aligned.m8n8.x4.shared.b16 {%0,%1,%2,%3}, [%4];"
                             : "=r"(ah[im][0]), "=r"(ah[im][1]), "=r"(ah[im][2]), "=r"(ah[im][3]) : "r"(adr));
                asm volatile("ldmatrix.sync.aligned.m8n8.x4.shared.b16 {%0,%1,%2,%3}, [%4];"
                             : "=r"(al[im][0]), "=r"(al[im][1]), "=r"(al[im][2]), "=r"(al[im][3]) : "r"(adr + 8192u));
            }
            #pragma unroll
            for (int in = 0; in < 4; ++in) {
                int r = wn + in * 8 + (lane & 7);
                int g = (ks << 1) + ((lane >> 3) & 1);
                uint32_t adr = base + 16384u + swz(r, g);
                asm volatile("ldmatrix.sync.aligned.m8n8.x2.shared.b16 {%0,%1}, [%2];"
                             : "=r"(bh[in][0]), "=r"(bh[in][1]) : "r"(adr));
                asm volatile("ldmatrix.sync.aligned.m8n8.x2.shared.b16 {%0,%1}, [%2];"
                             : "=r"(bl[in][0]), "=r"(bl[in][1]) : "r"(adr + 8192u));
            }
            #pragma unroll
            for (int im = 0; im < 4; ++im) {
                #pragma unroll
                for (int in = 0; in < 4; ++in) {
                    float* c = acc[im][in];
                    asm volatile("mma.sync.aligned.m16n8k16.row.col.f32.bf16.bf16.f32 "
                                 "{%0,%1,%2,%3},{%4,%5,%6,%7},{%8,%9},{%0,%1,%2,%3};"
                                 : "+f"(c[0]), "+f"(c[1]), "+f"(c[2]), "+f"(c[3])
                                 : "r"(ah[im][0]), "r"(ah[im][1]), "r"(ah[im][2]), "r"(ah[im][3]),
                                   "r"(bh[in][0]), "r"(bh[in][1]));
                    asm volatile("mma.sync.aligned.m16n8k16.row.col.f32.bf16.bf16.f32 "
                                 "{%0,%1,%2,%3},{%4,%5,%6,%7},{%8,%9},{%0,%1,%2,%3};"
                                 : "+f"(c[0]), "+f"(c[1]), "+f"(c[2]), "+f"(c[3])
                                 : "r"(ah[im][0]), "r"(ah[im][1]), "r"(ah[im][2]), "r"(ah[im][3]),
                                   "r"(bl[in][0]), "r"(bl[in][1]));
                    asm volatile("mma.sync.aligned.m16n8k16.row.col.f32.bf16.bf16.f32 "
                                 "{%0,%1,%2,%3},{%4,%5,%6,%7},{%8,%9},{%0,%1,%2,%3};"
                                 : "+f"(c[0]), "+f"(c[1]), "+f"(c[2]), "+f"(c[3])
                                 : "r"(al[im][0]), "r"(al[im][1]), "r"(al[im][2]), "r"(al[im][3]),
                                   "r"(bh[in][0]), "r"(bh[in][1]));
                }
            }
        }
        __syncthreads();
    }

    const int r0 = bm + wm + (lane >> 2);
    const int c0 = bn + wn + (lane & 3) * 2;
    #pragma unroll
    for (int im = 0; im < 4; ++im) {
        #pragma unroll
        for (int in = 0; in < 4; ++in) {
            int r = r0 + im * 16;
            int c = c0 + in * 8;
            float b0 = bias[c], b1 = bias[c + 1];
            float v0 = acc[im][in][0] + b0;
            float v1 = acc[im][in][1] + b1;
            float v2 = acc[im][in][2] + b0;
            float v3 = acc[im][in][3] + b1;
            if (RELU) {
                v0 = fmaxf(v0, 0.f); v1 = fmaxf(v1, 0.f);
                v2 = fmaxf(v2, 0.f); v3 = fmaxf(v3, 0.f);
            }
            if (OUT == 1) {
                __nv_bfloat16 h0, l0, h1, l1;
                split_bf16(v0, h0, l0); split_bf16(v1, h1, l1);
                uint32_t ph = (uint32_t)__bfloat16_as_ushort(h0) | ((uint32_t)__bfloat16_as_ushort(h1) << 16);
                uint32_t pl = (uint32_t)__bfloat16_as_ushort(l0) | ((uint32_t)__bfloat16_as_ushort(l1) << 16);
                *reinterpret_cast<uint32_t*>(Chi + (size_t)r * N + c) = ph;
                *reinterpret_cast<uint32_t*>(Clo + (size_t)r * N + c) = pl;
                split_bf16(v2, h0, l0); split_bf16(v3, h1, l1);
                ph = (uint32_t)__bfloat16_as_ushort(h0) | ((uint32_t)__bfloat16_as_ushort(h1) << 16);
                pl = (uint32_t)__bfloat16_as_ushort(l0) | ((uint32_t)__bfloat16_as_ushort(l1) << 16);
                *reinterpret_cast<uint32_t*>(Chi + (size_t)(r + 8) * N + c) = ph;
                *reinterpret_cast<uint32_t*>(Clo + (size_t)(r + 8) * N + c) = pl;
            } else if (OUT == 2) {
                *reinterpret_cast<__half2*>(Ch + (size_t)r * N + c) = __floats2half2_rn(v0, v1);
                *reinterpret_cast<__half2*>(Ch + (size_t)(r + 8) * N + c) = __floats2half2_rn(v2, v3);
            } else {
                *reinterpret_cast<float2*>(Cf + (size_t)r * N + c) = make_float2(v0, v1);
                *reinterpret_cast<float2*>(Cf + (size_t)(r + 8) * N + c) = make_float2(v2, v3);
            }
        }
    }
}

// ---------------------------------------------------------------------------
// MS-deform sampling, restructured: lane = (point, bilinear-row).
// Warp handles one (bs, h). Each lane owns point p = lane/2 and row j = lane&1,
// loads all 32 channels of its 2 corners (x0,yj),(x1,yj) via LDG.128,
// combines with fp32 corner weights, stages to smem, column-reduces.
// ---------------------------------------------------------------------------
__global__ __launch_bounds__(128)
void sample_kernel() {
    __shared__ float stage[4][32][36];
    const int wl = threadIdx.x >> 5;          // warp in block
    const int lane = threadIdx.x & 31;
    const int warp = blockIdx.x * 4 + wl;     // (bs, h)
    const int h = warp & 7;
    const int bs = warp >> 3;
    const int b = bs / S_TOTAL;
    const int s = bs - b * S_TOTAL;

    // ---- fused softmax over 16 logits (lanes 0-15 own one each) ----
    const float* logit_p = g_offattn + (size_t)bs * 384 + 256 + h * 16;
    float lg = (lane < 16) ? logit_p[lane] : -1e30f;
    float mxv = lg;
    #pragma unroll
    for (int o = 8; o > 0; o >>= 1) mxv = fmaxf(mxv, __shfl_xor_sync(0xffffffffu, mxv, o));
    float e = (lane < 16) ? expf(lg - mxv) : 0.f;
    float sm = e;
    #pragma unroll
    for (int o = 8; o > 0; o >>= 1) sm += __shfl_xor_sync(0xffffffffu, sm, o);
    float aw_lane = e / sm;

    // offsets: 32 floats, one per lane
    float off_lane = g_offattn[(size_t)bs * 384 + h * 32 + lane];

    // this lane's point / row
    const int p = lane >> 1;       // 0..15
    const int j = lane & 1;        // 0 -> y0 row, 1 -> y1 row
    const int l = p >> 2;          // level 0..3
    const int W = c_lvl_w[l], H = c_lvl_h[l], start = c_lvl_start[l];

    // query reference point (uniform across warp)
    int qlvl, qstart, qh, qw;
    level_of_s(s, qlvl, qstart, qh, qw);
    int qlocal = s - qstart;
    int qy = qlocal / qw;
    int qx = qlocal - qy * qw;
    float ref_x = (qx + 0.5f) / (float)qw;
    float ref_y = (qy + 0.5f) / (float)qh;

    // per-lane sampling location: (ref + off/W)*W - 0.5 == ref*W + off - 0.5
    float ox = __shfl_sync(0xffffffffu, off_lane, lane & 30);
    float oy = __shfl_sync(0xffffffffu, off_lane, (lane & 30) + 1);
    float aw = __shfl_sync(0xffffffffu, aw_lane, p);

    float x = fmaf(ref_x, (float)W, ox) - 0.5f;
    float y = fmaf(ref_y, (float)H, oy) - 0.5f;
    int x0 = __float2int_rd(x);
    int y0 = __float2int_rd(y);
    float lx = x - (float)x0;
    float ly = y - (float)y0;
    int yj = y0 + j;
    float wy = j ? ly : (1.f - ly);
    if ((unsigned)yj >= (unsigned)H) wy = 0.f;
    float wx0 = 1.f - lx;
    float wx1 = lx;
    if ((unsigned)x0 >= (unsigned)W) wx0 = 0.f;
    if ((unsigned)(x0 + 1) >= (unsigned)W) wx1 = 0.f;
    float aww = aw * wy;
    float W0 = aww * wx0;
    float W1 = aww * wx1;

    int cy  = min(max(yj, 0), H - 1);
    int cx0 = min(max(x0, 0), W - 1);
    int cx1 = min(max(x0 + 1, 0), W - 1);

    const __half* base = g_value + ((size_t)b * S_TOTAL + start + cy * W) * D + h * DH;
    const uint4* a0 = reinterpret_cast<const uint4*>(base + (size_t)cx0 * D);
    const uint4* a1 = reinterpret_cast<const uint4*>(base + (size_t)cx1 * D);

    // load both corners (8 outstanding LDG.128), then combine in fp32
    uint4 v0[4], v1[4];
    #pragma unroll
    for (int q = 0; q < 4; ++q) v0[q] = a0[q];
    #pragma unroll
    for (int q = 0; q < 4; ++q) v1[q] = a1[q];

    float* row = &stage[wl][lane][0];
    #pragma unroll
    for (int q = 0; q < 4; ++q) {
        const __half2* h0 = reinterpret_cast<const __half2*>(&v0[q]);
        const __half2* h1 = reinterpret_cast<const __half2*>(&v1[q]);
        float4 o0, o1;
        {
            float2 f0 = __half22float2(h0[0]);
            float2 g0 = __half22float2(h1[0]);
            float2 f1 = __half22float2(h0[1]);
            float2 g1 = __half22float2(h1[1]);
            o0.x = fmaf(W0, f0.x, W1 * g0.x);
            o0.y = fmaf(W0, f0.y, W1 * g0.y);
            o0.z = fmaf(W0, f1.x, W1 * g1.x);
            o0.w = fmaf(W0, f1.y, W1 * g1.y);
        }
        {
            float2 f2 = __half22float2(h0[2]);
            float2 g2 = __half22float2(h1[2]);
            float2 f3 = __half22float2(h0[3]);
            float2 g3 = __half22float2(h1[3]);
            o1.x = fmaf(W0, f2.x, W1 * g2.x);
            o1.y = fmaf(W0, f2.y, W1 * g2.y);
            o1.z = fmaf(W0, f3.x, W1 * g3.x);
            o1.w = fmaf(W0, f3.y, W1 * g3.y);
        }
        *reinterpret_cast<float4*>(row + q * 8)     = o0;
        *reinterpret_cast<float4*>(row + q * 8 + 4) = o1;
    }
    __syncwarp();

    // column reduction: lane = channel
    float r = 0.f;
    #pragma unroll
    for (int q = 0; q < 32; ++q) r += stage[wl][q][lane];

    size_t oidx = (size_t)bs * D + h * DH + lane;
    __nv_bfloat16 hh, ll;
    split_bf16(r, hh, ll);
    g_attn_hi[oidx] = hh;
    g_attn_lo[oidx] = ll;
}

// ---------------------------------------------------------------------------
// dst = LayerNorm(x + y); optional bf16 hi/lo; optional q=dst+pos hi/lo
// ---------------------------------------------------------------------------
__global__ __launch_bounds__(256)
void residual_ln_kernel(const float* __restrict__ x, const float* __restrict__ y,
                        const float* __restrict__ gamma, const float* __restrict__ beta,
                        float* __restrict__ dst,
                        __nv_bfloat16* __restrict__ dhi, __nv_bfloat16* __restrict__ dlo,
                        const float* __restrict__ pos,
                        __nv_bfloat16* __restrict__ qhi, __nv_bfloat16* __restrict__ qlo) {
    int row = (blockIdx.x * blockDim.x + threadIdx.x) >> 5;
    int lane = threadIdx.x & 31;
    if (row >= M_ROWS) return;
    const float* xr = x + (size_t)row * D + lane * 8;
    const float* yr = y + (size_t)row * D + lane * 8;
    float v[8];
    float s = 0.f;
    #pragma unroll
    for (int i = 0; i < 8; ++i) { v[i] = xr[i] + yr[i]; s += v[i]; }
    #pragma unroll
    for (int o = 16; o > 0; o >>= 1) s += __shfl_xor_sync(0xffffffffu, s, o);
    float mean = s * (1.f / D);
    float vs = 0.f;
    #pragma unroll
    for (int i = 0; i < 8; ++i) { float d = v[i] - mean; vs += d * d; }
    #pragma unroll
    for (int o = 16; o > 0; o >>= 1) vs += __shfl_xor_sync(0xffffffffu, vs, o);
    float rstd = rsqrtf(vs * (1.f / D) + 1e-5f);

    size_t base = (size_t)row * D + lane * 8;
    float* dr = dst + base;
    float w[8];
    #pragma unroll
    for (int i = 0; i < 8; ++i) {
        int c = lane * 8 + i;
        w[i] = (v[i] - mean) * rstd * gamma[c] + beta[c];
        dr[i] = w[i];
    }
    if (dhi) {
        uint32_t ph[4], pl[4];
        #pragma unroll
        for (int p = 0; p < 4; ++p) {
            __nv_bfloat16 h0, l0, h1, l1;
            split_bf16(w[2 * p], h0, l0);
            split_bf16(w[2 * p + 1], h1, l1);
            ph[p] = (uint32_t)__bfloat16_as_ushort(h0) | ((uint32_t)__bfloat16_as_ushort(h1) << 16);
            pl[p] = (uint32_t)__bfloat16_as_ushort(l0) | ((uint32_t)__bfloat16_as_ushort(l1) << 16);
        }
        *reinterpret_cast<uint4*>(dhi + base) = make_uint4(ph[0], ph[1], ph[2], ph[3]);
        *reinterpret_cast<uint4*>(dlo + base) = make_uint4(pl[0], pl[1], pl[2], pl[3]);
    }
    if (qhi) {
        const float* pr = pos + base;
        uint32_t ph[4], pl[4];
        #pragma unroll
        for (int p = 0; p < 4; ++p) {
            __nv_bfloat16 h0, l0, h1, l1;
            split_bf16(w[2 * p] + pr[2 * p], h0, l0);
            split_bf16(w[2 * p + 1] + pr[2 * p + 1], h1, l1);
            ph[p] = (uint32_t)__bfloat16_as_ushort(h0) | ((uint32_t)__bfloat16_as_ushort(h1) << 16);
            pl[p] = (uint32_t)__bfloat16_as_ushort(l0) | ((uint32_t)__bfloat16_as_ushort(l1) << 16);
        }
        *reinterpret_cast<uint4*>(qhi + base) = make_uint4(ph[0], ph[1], ph[2], ph[3]);
        *reinterpret_cast<uint4*>(qlo + base) = make_uint4(pl[0], pl[1], pl[2], pl[3]);
    }
}

// ---------------------------------------------------------------------------
// host launcher
// ---------------------------------------------------------------------------
extern "C" void kernel_launch(void* const* d_in, const int* in_sizes, int n_in,
                              void* d_out, int out_size) {
    const int lvl_elems[NL] = {
        BATCH * D * 128 * 128, BATCH * D * 64 * 64,
        BATCH * D * 32 * 32,   BATCH * D * 16 * 16
    };
    const float* srcp[NL] = {0, 0, 0, 0};
    const float* posp[NL] = {0, 0, 0, 0};
    for (int i = 0; i < 8; ++i) {
        int sz = in_sizes[i];
        for (int l = 0; l < NL; ++l) {
            if (sz == lvl_elems[l]) {
                if (!srcp[l]) srcp[l] = (const float*)d_in[i];
                else if (!posp[l]) posp[l] = (const float*)d_in[i];
                break;
            }
        }
    }

    const float* level_embed = (const float*)d_in[8];
    const float* Woff  = (const float*)d_in[9];
    const float* boff  = (const float*)d_in[10];
    const float* Wattn = (const float*)d_in[11];
    const float* battn = (const float*)d_in[12];
    const float* Wval  = (const float*)d_in[13];
    const float* bval  = (const float*)d_in[14];
    const float* Wout  = (const float*)d_in[15];
    const float* bout  = (const float*)d_in[16];
    const float* ln1_s = (const float*)d_in[17];
    const float* ln1_b = (const float*)d_in[18];
    const float* W1    = (const float*)d_in[19];
    const float* b1    = (const float*)d_in[20];
    const float* W2    = (const float*)d_in[21];
    const float* b2    = (const float*)d_in[22];
    const float* ln2_s = (const float*)d_in[23];
    const float* ln2_b = (const float*)d_in[24];
    float* out = (float*)d_out;

    float *p_pos, *p_out, *p_offattn, *p_proj, *p_ffn2, *p_bcomb;
    __half* p_value;
    __nv_bfloat16 *p_out_hi, *p_out_lo, *p_q_hi, *p_q_lo, *p_ln1_hi, *p_ln1_lo,
                  *p_attn_hi, *p_attn_lo, *p_f1_hi, *p_f1_lo;
    __nv_bfloat16 *p_WvalT_hi, *p_WvalT_lo, *p_WcombT_hi, *p_WcombT_lo,
                  *p_WoutT_hi, *p_WoutT_lo, *p_W1T_hi, *p_W1T_lo, *p_W2T_hi, *p_W2T_lo;
    cudaGetSymbolAddress((void**)&p_pos, g_pos);
    cudaGetSymbolAddress((void**)&p_out, g_out);
    cudaGetSymbolAddress((void**)&p_value, g_value);
    cudaGetSymbolAddress((void**)&p_offattn, g_offattn);
    cudaGetSymbolAddress((void**)&p_proj, g_proj);
    cudaGetSymbolAddress((void**)&p_ffn2, g_ffn2);
    cudaGetSymbolAddress((void**)&p_bcomb, g_bcomb);
    cudaGetSymbolAddress((void**)&p_out_hi, g_out_hi);
    cudaGetSymbolAddress((void**)&p_out_lo, g_out_lo);
    cudaGetSymbolAddress((void**)&p_q_hi, g_q_hi);
    cudaGetSymbolAddress((void**)&p_q_lo, g_q_lo);
    cudaGetSymbolAddress((void**)&p_ln1_hi, g_ln1_hi);
    cudaGetSymbolAddress((void**)&p_ln1_lo, g_ln1_lo);
    cudaGetSymbolAddress((void**)&p_attn_hi, g_attn_hi);
    cudaGetSymbolAddress((void**)&p_attn_lo, g_attn_lo);
    cudaGetSymbolAddress((void**)&p_f1_hi, g_f1_hi);
    cudaGetSymbolAddress((void**)&p_f1_lo, g_f1_lo);
    cudaGetSymbolAddress((void**)&p_WvalT_hi, g_WvalT_hi);
    cudaGetSymbolAddress((void**)&p_WvalT_lo, g_WvalT_lo);
    cudaGetSymbolAddress((void**)&p_WcombT_hi, g_WcombT_hi);
    cudaGetSymbolAddress((void**)&p_WcombT_lo, g_WcombT_lo);
    cudaGetSymbolAddress((void**)&p_WoutT_hi, g_WoutT_hi);
    cudaGetSymbolAddress((void**)&p_WoutT_lo, g_WoutT_lo);
    cudaGetSymbolAddress((void**)&p_W1T_hi, g_W1T_hi);
    cudaGetSymbolAddress((void**)&p_W1T_lo, g_W1T_lo);
    cudaGetSymbolAddress((void**)&p_W2T_hi, g_W2T_hi);
    cudaGetSymbolAddress((void**)&p_W2T_lo, g_W2T_lo);

    cudaFuncSetAttribute(gemm_mma<false, 0>, cudaFuncAttributeMaxDynamicSharedMemorySize, GM_SMEM);
    cudaFuncSetAttribute(gemm_mma<false, 2>, cudaFuncAttributeMaxDynamicSharedMemorySize, GM_SMEM);
    cudaFuncSetAttribute(gemm_mma<true, 1>,  cudaFuncAttributeMaxDynamicSharedMemorySize, GM_SMEM);

    const int TB = 256;
    const size_t total = (size_t)M_ROWS * D;
    const int elem_blocks = (int)((total + TB - 1) / TB);

    {
        unsigned n = NLAYERS * PER_LAYER_W;
        wsplit_all_kernel<<<(n + 255) / 256, 256>>>(Wval, Woff, Wattn, Wout, W1, W2);
        bcomb_kernel<<<(NLAYERS * 384 + 255) / 256, 256>>>(boff, battn);
    }

    flatten_kernel<<<elem_blocks, TB>>>(srcp[0], srcp[1], srcp[2], srcp[3],
                                        posp[0], posp[1], posp[2], posp[3], level_embed);

    const dim3 gblk(256);
    const int sample_blocks = (M_ROWS * NH) / 4;   // 4 warps per block, exact
    for (int i = 0; i < NLAYERS; ++i) {
        // value = out @ Wval + bval -> fp16
        gemm_mma<false, 2><<<dim3(2, M_ROWS / 128), gblk, GM_SMEM>>>(
            p_out_hi, p_out_lo,
            p_WvalT_hi + (size_t)i * 256 * 256, p_WvalT_lo + (size_t)i * 256 * 256,
            bval + (size_t)i * 256, 0, 0, 0, p_value, 256, 256);
        // [off | attn logits] = q @ Wcomb + bcomb
        gemm_mma<false, 0><<<dim3(3, M_ROWS / 128), gblk, GM_SMEM>>>(
            p_q_hi, p_q_lo,
            p_WcombT_hi + (size_t)i * 384 * 256, p_WcombT_lo + (size_t)i * 384 * 256,
            p_bcomb + (size_t)i * 384, p_offattn, 0, 0, 0, 384, 256);
        // deform sampling (softmax fused) -> attn hi/lo
        sample_kernel<<<sample_blocks, 128>>>();
        // proj = attnout @ Wout + bout
        gemm_mma<false, 0><<<dim3(2, M_ROWS / 128), gblk, GM_SMEM>>>(
            p_attn_hi, p_attn_lo,
            p_WoutT_hi + (size_t)i * 256 * 256, p_WoutT_lo + (size_t)i * 256 * 256,
            bout + (size_t)i * 256, p_proj, 0, 0, 0, 256, 256);
        // out = LN(out + proj), + ln1 hi/lo
        residual_ln_kernel<<<(M_ROWS * 32 + TB - 1) / TB, TB>>>(
            p_out, p_proj, ln1_s + (size_t)i * 256, ln1_b + (size_t)i * 256,
            p_out, p_ln1_hi, p_ln1_lo, (const float*)0, (__nv_bfloat16*)0, (__nv_bfloat16*)0);
        // ffn1 = relu(ln1 @ W1 + b1) -> bf16 hi/lo
        gemm_mma<true, 1><<<dim3(8, M_ROWS / 128), gblk, GM_SMEM>>>(
            p_ln1_hi, p_ln1_lo,
            p_W1T_hi + (size_t)i * 1024 * 256, p_W1T_lo + (size_t)i * 1024 * 256,
            b1 + (size_t)i * 1024, 0, p_f1_hi, p_f1_lo, 0, 1024, 256);
        // ffn2 = ffn1 @ W2 + b2
        gemm_mma<false, 0><<<dim3(2, M_ROWS / 128), gblk, GM_SMEM>>>(
            p_f1_hi, p_f1_lo,
            p_W2T_hi + (size_t)i * 256 * 1024, p_W2T_lo + (size_t)i * 256 * 1024,
            b2 + (size_t)i * 256, p_ffn2, 0, 0, 0, 256, 1024);
        // out = LN(out + ffn2)
        if (i == NLAYERS - 1) {
            residual_ln_kernel<<<(M_ROWS * 32 + TB - 1) / TB, TB>>>(
                p_out, p_ffn2, ln2_s + (size_t)i * 256, ln2_b + (size_t)i * 256,
                out, (__nv_bfloat16*)0, (__nv_bfloat16*)0,
                (const float*)0, (__nv_bfloat16*)0, (__nv_bfloat16*)0);
        } else {
            residual_ln_kernel<<<(M_ROWS * 32 + TB - 1) / TB, TB>>>(
                p_out, p_ffn2, ln2_s + (size_t)i * 256, ln2_b + (size_t)i * 256,
                p_out, p_out_hi, p_out_lo, p_pos, p_q_hi, p_q_lo);
        }
    }
}